// round 13
// baseline (speedup 1.0000x reference)
#include <cuda_runtime.h>
#include <cuda_fp16.h>
#include <cstdint>

#define B_  4
#define S_  2048
#define D_  1024
#define H_  16
#define M_TOT 8192

// ---------------- device scratch (no allocs allowed) ----------------
__device__ __align__(256) __half g_qh[M_TOT * D_], g_ql[M_TOT * D_];
__device__ __align__(256) __half g_kh[M_TOT * D_], g_kl[M_TOT * D_];
__device__ __align__(256) __half g_vh[M_TOT * D_];
__device__ __align__(256) __half g_wqh[H_ * 64 * D_], g_wql[H_ * 64 * D_];
__device__ __align__(256) __half g_wkh[H_ * 64 * D_], g_wkl[H_ * 64 * D_];
__device__ __align__(256) __half g_wvh[H_ * 64 * D_];
__device__ __align__(256) __half g_woh[D_ * D_];
__device__ __align__(256) __half g_Qh[64 * S_ * 64];     // [bh][s][dk] hi only (pre-scaled)
__device__ __align__(256) __half g_Kh[64 * S_ * 64];     // [bh][key][dk] hi only (3-term-accurate, rounded once)
__device__ __align__(256) __half g_Vth[64 * 64 * S_];    // [bh][dv][key] hi only
__device__ __align__(256) __half g_Hh[M_TOT * D_];       // hi only

// ---------------- PTX helpers (baseline ISA: sm_80+) ----------------
__device__ __forceinline__ uint32_t smem_u32(const void* p) {
    uint32_t a;
    asm("{ .reg .u64 t; cvta.to.shared.u64 t, %1; cvt.u32.u64 %0, t; }"
        : "=r"(a) : "l"(p));
    return a;
}
__device__ __forceinline__ void cp16(uint32_t dst, const void* src) {
    asm volatile("cp.async.cg.shared.global [%0], [%1], 16;"
                 :: "r"(dst), "l"(src) : "memory");
}
#define CP_COMMIT() asm volatile("cp.async.commit_group;" ::: "memory")
#define CP_WAIT1()  asm volatile("cp.async.wait_group 1;"  ::: "memory")
#define CP_WAIT0()  asm volatile("cp.async.wait_group 0;"  ::: "memory")

__device__ __forceinline__ void ldsm_x4(uint32_t* r, uint32_t addr) {
    asm volatile("ldmatrix.sync.aligned.m8n8.x4.shared.b16 {%0,%1,%2,%3}, [%4];"
                 : "=r"(r[0]), "=r"(r[1]), "=r"(r[2]), "=r"(r[3]) : "r"(addr));
}
// fp16 inputs, fp32 accumulate (fastest legacy path per r7/r8 measurements)
__device__ __forceinline__ void hmma(float* d, const uint32_t* a,
                                     uint32_t b0, uint32_t b1) {
    asm volatile("mma.sync.aligned.m16n8k16.row.col.f32.f16.f16.f32 "
                 "{%0,%1,%2,%3}, {%4,%5,%6,%7}, {%8,%9}, {%0,%1,%2,%3};"
                 : "+f"(d[0]), "+f"(d[1]), "+f"(d[2]), "+f"(d[3])
                 : "r"(a[0]), "r"(a[1]), "r"(a[2]), "r"(a[3]), "r"(b0), "r"(b1));
}
__device__ __forceinline__ uint32_t swz(uint32_t off) {
    return off ^ ((off >> 3) & 0x70);
}
__device__ __forceinline__ void split_f16(float x, __half& h, __half& l) {
    h = __float2half_rn(x);
    l = __float2half_rn(x - __half2float(h));
}
__device__ __forceinline__ uint32_t pack2(float x, float y) {
    __half2 h = __floats2half2_rn(x, y);
    return *reinterpret_cast<uint32_t*>(&h);
}

// ---------------- conversion kernels (fused) ----------------
__global__ __launch_bounds__(256) void conv_in3(const float* __restrict__ q,
                                                const float* __restrict__ k,
                                                const float* __restrict__ v)
{
    const int which = blockIdx.y;
    const float* x = (which == 0) ? q : ((which == 1) ? k : v);
    __half* hi = (which == 0) ? g_qh : ((which == 1) ? g_kh : g_vh);
    __half* lo = (which == 0) ? g_ql : g_kl;   // V needs no lo (1-term proj)
    size_t i = ((size_t)blockIdx.x * 256 + threadIdx.x) * 4;
    float4 vv = *reinterpret_cast<const float4*>(x + i);
    __half h0, h1, h2, h3, l0, l1, l2, l3;
    split_f16(vv.x, h0, l0); split_f16(vv.y, h1, l1);
    split_f16(vv.z, h2, l2); split_f16(vv.w, h3, l3);
    *reinterpret_cast<__half2*>(hi + i)     = __halves2half2(h0, h1);
    *reinterpret_cast<__half2*>(hi + i + 2) = __halves2half2(h2, h3);
    if (which != 2) {
        *reinterpret_cast<__half2*>(lo + i)     = __halves2half2(l0, l1);
        *reinterpret_cast<__half2*>(lo + i + 2) = __halves2half2(l2, l3);
    }
}

// z=0..2: W[h][k][n] (16,1024,64) -> Wt[h][n][k] hi (and lo for Q/K)
// z=3:    Wo[k][n] (1024,1024) -> Wot[n][k] hi
__global__ __launch_bounds__(256) void conv_w4(const float* __restrict__ Wq,
                                               const float* __restrict__ Wk,
                                               const float* __restrict__ Wv,
                                               const float* __restrict__ Wo)
{
    const int which = blockIdx.y;
    int idx = blockIdx.x * 256 + threadIdx.x;
    if (which == 3) {
        int k = idx & 1023;
        int n = idx >> 10;
        g_woh[idx] = __float2half_rn(Wo[(size_t)k * D_ + n]);
        return;
    }
    const float* W = (which == 0) ? Wq : ((which == 1) ? Wk : Wv);
    __half* hi = (which == 0) ? g_wqh : ((which == 1) ? g_wkh : g_wvh);
    __half* lo = (which == 0) ? g_wql : g_wkl;
    int k = idx & 1023;
    int n = (idx >> 10) & 63;
    int h = idx >> 16;
    float x = W[((size_t)h * D_ + k) * 64 + n];
    __half hh, ll;
    split_f16(x, hh, ll);
    hi[idx] = hh;
    if (which != 2) lo[idx] = ll;
}

// ---------------- split-fp16 HMMA GEMM (256 thr, 8 warps x 16 rows) ----------------
// terms per mode: Q(0)=3, K(1)=3 (accurate then rounded once), V(2)=1, out(3)=1.
// mode 4: z-merged Q/K/V projections.
#define STAGE_BYTES 49152
#define A_HI_OFF 0
#define A_LO_OFF 16384
#define B_HI_OFF 32768
#define B_LO_OFF 40960
#define MMA_SMEM (2 * STAGE_BYTES)

__global__ __launch_bounds__(256) void mma_gemm(const __half* __restrict__ ah_,
                                                const __half* __restrict__ bh_,
                                                const __half* __restrict__ bl_,
                                                float* __restrict__ outp, int mode)
{
    extern __shared__ char sm[];
    const uint32_t smem = smem_u32(sm);
    const int tid  = threadIdx.x;
    const int wid  = tid >> 5;
    const int lane = tid & 31;
    const int nb   = blockIdx.x;
    const int m0   = blockIdx.y * 128;
    const int mbase = wid * 16;

    int emode = mode;
    const __half *ah = ah_, *al = nullptr, *bh = bh_, *bl = bl_;
    if (mode == 4) {
        const int z = blockIdx.z;          // 0=Q 1=K 2=V
        emode = z;
        ah = (z == 0) ? g_qh : ((z == 1) ? g_kh : g_vh);
        al = (z == 0) ? g_ql : g_kl;
        bh = (z == 0) ? g_wqh : ((z == 1) ? g_wkh : g_wvh);
        bl = (z == 0) ? g_wql : g_wkl;
    }
    const int nt = (emode <= 1) ? 3 : 1;   // Q/K: 3-term; V/out: 1-term

    const __half* aH = ah + (size_t)m0 * D_;
    const __half* aL = (nt >= 3) ? (al + (size_t)m0 * D_) : nullptr;
    const __half* bH = bh + (size_t)nb * 64 * D_;
    const __half* bL = (nt >= 2) ? (bl + (size_t)nb * 64 * D_) : nullptr;

    const int arow = tid >> 1, ahalf = tid & 1;
    const int brow_ = tid >> 2, bq = tid & 3;
    auto load_stage = [&](int c, int buf) {
        const uint32_t sb = smem + buf * STAGE_BYTES;
        const int k0 = c * 64;
        const char* gh = (const char*)(aH + (size_t)arow * D_ + k0) + ahalf * 64;
        #pragma unroll
        for (int j = 0; j < 4; ++j) {
            uint32_t sw = swz(arow * 128 + ahalf * 64 + j * 16);
            cp16(sb + A_HI_OFF + sw, gh + j * 16);
            if (nt >= 3) {
                const char* gl = (const char*)(aL + (size_t)arow * D_ + k0) + ahalf * 64;
                cp16(sb + A_LO_OFF + sw, gl + j * 16);
            }
        }
        const char* gbh = (const char*)(bH + (size_t)brow_ * D_ + k0) + bq * 32;
        #pragma unroll
        for (int j = 0; j < 2; ++j) {
            uint32_t sw = swz(brow_ * 128 + bq * 32 + j * 16);
            cp16(sb + B_HI_OFF + sw, gbh + j * 16);
            if (nt >= 2) {
                const char* gbl = (const char*)(bL + (size_t)brow_ * D_ + k0) + bq * 32;
                cp16(sb + B_LO_OFF + sw, gbl + j * 16);
            }
        }
    };

    float acc[8][4] = {};

    load_stage(0, 0);
    CP_COMMIT();

    for (int c = 0; c < 16; ++c) {
        const int buf = c & 1;
        if (c < 15) { load_stage(c + 1, buf ^ 1); CP_COMMIT(); }
        if (c < 15) CP_WAIT1(); else CP_WAIT0();
        __syncthreads();

        const uint32_t sb = smem + buf * STAGE_BYTES;
        #pragma unroll
        for (int ks = 0; ks < 4; ++ks) {
            const int kb = ks * 32;
            uint32_t ahi[4], alo[4];
            {
                uint32_t off = (uint32_t)(mbase + (lane & 15)) * 128
                             + kb + (lane >> 4) * 16;
                uint32_t sw = swz(off);
                ldsm_x4(ahi, sb + A_HI_OFF + sw);
                if (nt >= 3) ldsm_x4(alo, sb + A_LO_OFF + sw);
            }
            uint32_t bhi[4][4], blo[4][4];
            #pragma unroll
            for (int np = 0; np < 4; ++np) {
                uint32_t n  = np * 16 + (lane & 7) + ((lane >> 4) << 3);
                uint32_t off = n * 128 + kb + ((lane >> 3) & 1) * 16;
                uint32_t sw = swz(off);
                ldsm_x4(bhi[np], sb + B_HI_OFF + sw);
                if (nt >= 2) ldsm_x4(blo[np], sb + B_LO_OFF + sw);
            }
            #pragma unroll
            for (int nf = 0; nf < 8; ++nf) {
                const int np = nf >> 1, sel = (nf & 1) * 2;
                hmma(acc[nf], ahi, bhi[np][sel], bhi[np][sel + 1]);
            }
            if (nt >= 2) {
                #pragma unroll
                for (int nf = 0; nf < 8; ++nf) {
                    const int np = nf >> 1, sel = (nf & 1) * 2;
                    hmma(acc[nf], ahi, blo[np][sel], blo[np][sel + 1]);
                }
            }
            if (nt >= 3) {
                #pragma unroll
                for (int nf = 0; nf < 8; ++nf) {
                    const int np = nf >> 1, sel = (nf & 1) * 2;
                    hmma(acc[nf], alo, bhi[np][sel], bhi[np][sel + 1]);
                }
            }
        }
        __syncthreads();
    }

    // ---- epilogue ----
    const int g = lane >> 2;
    const int t = lane & 3;
    #pragma unroll
    for (int half = 0; half < 2; ++half) {
        const int m = m0 + mbase + half * 8 + g;
        if (emode == 3) {
            float* orow = outp + (size_t)m * D_ + nb * 64;
            #pragma unroll
            for (int nf = 0; nf < 8; ++nf)
                *reinterpret_cast<float2*>(orow + nf * 8 + t * 2) =
                    make_float2(acc[nf][half * 2], acc[nf][half * 2 + 1]);
        } else {
            const int b = m >> 11, s = m & (S_ - 1);
            const int bh_i = b * H_ + nb;
            if (emode == 0) {
                // Q: hi only, pre-scaled
                size_t base = ((size_t)bh_i * S_ + s) * 64;
                #pragma unroll
                for (int nf = 0; nf < 8; ++nf)
                    *reinterpret_cast<uint32_t*>(g_Qh + base + nf * 8 + t * 2) =
                        pack2(acc[nf][half * 2] * 0.125f, acc[nf][half * 2 + 1] * 0.125f);
            } else if (emode == 1) {
                // K: hi only (rounded once from accurate 3-term f32)
                size_t base = ((size_t)bh_i * S_ + s) * 64;
                #pragma unroll
                for (int nf = 0; nf < 8; ++nf)
                    *reinterpret_cast<uint32_t*>(g_Kh + base + nf * 8 + t * 2) =
                        pack2(acc[nf][half * 2], acc[nf][half * 2 + 1]);
            } else {
                // V transpose: (s=key, dv) -> [bh][dv][key], hi only
                #pragma unroll
                for (int nf = 0; nf < 8; ++nf) {
                    #pragma unroll
                    for (int e = 0; e < 2; ++e) {
                        int dv = nf * 8 + t * 2 + e;
                        size_t addr = ((size_t)bh_i * 64 + dv) * S_ + s;
                        g_Vth[addr] = __float2half_rn(acc[nf][half * 2 + e]);
                    }
                }
            }
        }
    }
}

// ---------------- tensor-core flash attention ----------------
// 64-row q-tiles, 128 threads (4 warps x 16 rows), 5 CTAs/SM for wave balance.
// QK^T: 1-term (Qh*Kh). PV: 1-term (P rounded fp16, V hi).
#define KH_OFF 0
#define VH_OFF 8192
#define AT_STAGE 16384
#define QH_OFF (2 * AT_STAGE)
#define ATT_SMEM (QH_OFF + 8192)

__global__ __launch_bounds__(128, 5) void attn_mma()
{
    extern __shared__ char sm[];
    const uint32_t smem = smem_u32(sm);
    const int tid  = threadIdx.x;
    const int wid  = tid >> 5;       // 0..3
    const int lane = tid & 31;
    const int bh   = blockIdx.y;
    const int q0   = blockIdx.x * 64;
    const int mbase = wid * 16;      // rows 0..63 within tile

    // Q tile async load (hi only): 64 rows x 128B, 2 threads per row
    {
        const int row = tid >> 1, half = tid & 1;
        const char* gh = (const char*)(g_Qh + ((size_t)bh * S_ + q0 + row) * 64) + half * 64;
        #pragma unroll
        for (int i = 0; i < 4; ++i) {
            uint32_t sw = swz(row * 128 + half * 64 + i * 16);
            cp16(smem + QH_OFF + sw, gh + i * 16);
        }
    }
    const int r2 = tid >> 1, hf = tid & 1;
    auto load_stage = [&](int kt, int buf) {
        const uint32_t sb = smem + buf * AT_STAGE;
        const char* kh = (const char*)(g_Kh + ((size_t)bh * S_ + kt + r2) * 64) + hf * 64;
        const char* vh = (const char*)(g_Vth + ((size_t)bh * 64 + r2) * S_ + kt) + hf * 64;
        #pragma unroll
        for (int j = 0; j < 4; ++j) {
            uint32_t sw = swz(r2 * 128 + hf * 64 + j * 16);
            cp16(sb + KH_OFF + sw, kh + j * 16);
            cp16(sb + VH_OFF + sw, vh + j * 16);
        }
    };
    load_stage(0, 0);  CP_COMMIT();
    load_stage(64, 1); CP_COMMIT();
    CP_WAIT1();
    __syncthreads();

    // persistent Q hi fragments
    uint32_t qh[4][4];
    #pragma unroll
    for (int ks = 0; ks < 4; ++ks) {
        uint32_t off = (uint32_t)(mbase + (lane & 15)) * 128
                     + ks * 32 + (lane >> 4) * 16;
        ldsm_x4(qh[ks], smem + QH_OFF + swz(off));
    }

    float O[8][4] = {};
    float mrow[2] = {-1e30f, -1e30f};
    float lrow[2] = {};

    for (int c = 0; c < 32; ++c) {
        const uint32_t sb = smem + (c & 1) * AT_STAGE;

        // ---- QK^T (1-term: Qh*Kh) ----
        float s[8][4] = {};
        #pragma unroll
        for (int ks = 0; ks < 4; ++ks) {
            #pragma unroll
            for (int np2 = 0; np2 < 2; ++np2) {
                uint32_t kbh2[2][4];
                #pragma unroll
                for (int j = 0; j < 2; ++j) {
                    const int np = np2 * 2 + j;
                    uint32_t n  = np * 16 + (lane & 7) + ((lane >> 4) << 3);
                    uint32_t off = n * 128 + ks * 32 + ((lane >> 3) & 1) * 16;
                    ldsm_x4(kbh2[j], sb + KH_OFF + swz(off));
                }
                #pragma unroll
                for (int j = 0; j < 4; ++j) {
                    const int p = j >> 1, sel = (j & 1) * 2;
                    hmma(s[np2 * 4 + j], qh[ks], kbh2[p][sel], kbh2[p][sel + 1]);
                }
            }
        }

        // ---- online softmax (warp-uniform skip of rescale when max unchanged) ----
        #pragma unroll
        for (int half = 0; half < 2; ++half) {
            float rmax = -1e30f;
            #pragma unroll
            for (int nf = 0; nf < 8; ++nf)
                rmax = fmaxf(rmax, fmaxf(s[nf][half * 2], s[nf][half * 2 + 1]));
            rmax = fmaxf(rmax, __shfl_xor_sync(0xffffffffu, rmax, 1));
            rmax = fmaxf(rmax, __shfl_xor_sync(0xffffffffu, rmax, 2));
            if (__any_sync(0xffffffffu, rmax > mrow[half])) {
                const float mnew = fmaxf(mrow[half], rmax);
                const float corr = __expf(mrow[half] - mnew);
                lrow[half] *= corr;
                mrow[half] = mnew;
                #pragma unroll
                for (int nf = 0; nf < 8; ++nf) {
                    O[nf][half * 2]     *= corr;
                    O[nf][half * 2 + 1] *= corr;
                }
            }
            float rsum = 0.0f;
            #pragma unroll
            for (int nf = 0; nf < 8; ++nf) {
                float p0 = __expf(s[nf][half * 2]     - mrow[half]);
                float p1 = __expf(s[nf][half * 2 + 1] - mrow[half]);
                s[nf][half * 2]     = p0;
                s[nf][half * 2 + 1] = p1;
                rsum += p0 + p1;
            }
            rsum += __shfl_xor_sync(0xffffffffu, rsum, 1);
            rsum += __shfl_xor_sync(0xffffffffu, rsum, 2);
            lrow[half] += rsum;
        }

        // ---- P @ V (1-term: P rounded fp16, V hi) ----
        #pragma unroll
        for (int kk = 0; kk < 4; ++kk) {
            uint32_t pah[4];
            pah[0] = pack2(s[2 * kk][0],     s[2 * kk][1]);
            pah[1] = pack2(s[2 * kk][2],     s[2 * kk][3]);
            pah[2] = pack2(s[2 * kk + 1][0], s[2 * kk + 1][1]);
            pah[3] = pack2(s[2 * kk + 1][2], s[2 * kk + 1][3]);
            #pragma unroll
            for (int np2 = 0; np2 < 2; ++np2) {
                uint32_t vbh2[2][4];
                #pragma unroll
                for (int j = 0; j < 2; ++j) {
                    const int np = np2 * 2 + j;
                    uint32_t n  = np * 16 + (lane & 7) + ((lane >> 4) << 3);
                    uint32_t off = n * 128 + kk * 32 + ((lane >> 3) & 1) * 16;
                    ldsm_x4(vbh2[j], sb + VH_OFF + swz(off));
                }
                #pragma unroll
                for (int j = 0; j < 4; ++j) {
                    const int p = j >> 1, sel = (j & 1) * 2;
                    hmma(O[np2 * 4 + j], pah, vbh2[p][sel], vbh2[p][sel + 1]);
                }
            }
        }

        __syncthreads();
        if (c + 2 < 32) {
            load_stage((c + 2) * 64, c & 1);
            CP_COMMIT();
            CP_WAIT1();
        } else if (c + 1 < 32) {
            CP_WAIT0();
        }
        __syncthreads();
    }

    // ---- epilogue: normalize, round to fp16 hi, concat-head layout ----
    const int b = bh >> 4, h = bh & 15;
    const int g = lane >> 2, t = lane & 3;
    #pragma unroll
    for (int half = 0; half < 2; ++half) {
        const float inv = 1.0f / lrow[half];
        const int srow = q0 + mbase + half * 8 + g;
        size_t base = ((size_t)(b * S_ + srow)) * D_ + h * 64;
        #pragma unroll
        for (int nf = 0; nf < 8; ++nf) {
            uint32_t hi = pack2(O[nf][half * 2] * inv, O[nf][half * 2 + 1] * inv);
            *reinterpret_cast<uint32_t*>(g_Hh + base + nf * 8 + t * 2) = hi;
        }
    }
}

// ---------------- launch ----------------
extern "C" void kernel_launch(void* const* d_in, const int* in_sizes, int n_in,
                              void* d_out, int out_size)
{
    const float* q  = (const float*)d_in[0];
    const float* k  = (const float*)d_in[1];
    const float* v  = (const float*)d_in[2];
    const float* Wq = (const float*)d_in[3];
    const float* Wk = (const float*)d_in[4];
    const float* Wv = (const float*)d_in[5];
    const float* Wo = (const float*)d_in[6];
    float* out = (float*)d_out;

    static bool configured = false;
    if (!configured) {
        cudaFuncSetAttribute(mma_gemm, cudaFuncAttributeMaxDynamicSharedMemorySize, MMA_SMEM);
        cudaFuncSetAttribute(attn_mma, cudaFuncAttributeMaxDynamicSharedMemorySize, ATT_SMEM);
        configured = true;
    }

    __half *woh, *Hh;
    cudaGetSymbolAddress((void**)&woh, g_woh);
    cudaGetSymbolAddress((void**)&Hh, g_Hh);

    conv_in3<<<dim3(8192, 3), 256>>>(q, k, v);
    conv_w4<<<dim3(4096, 4), 256>>>(Wq, Wk, Wv, Wo);

    // merged Q/K/V projections: one launch, z = which (Q/K 3-term, V 1-term)
    dim3 proj_grid(H_, M_TOT / 128, 3);
    mma_gemm<<<proj_grid, 256, MMA_SMEM>>>(nullptr, nullptr, nullptr, nullptr, 4);

    dim3 attn_grid(S_ / 64, B_ * H_);    // 32 x 64
    attn_mma<<<attn_grid, 128, ATT_SMEM>>>();

    // out projection: 1-term (H hi, Wo hi)
    dim3 out_grid(D_ / 64, M_TOT / 128); // 16 x 64
    mma_gemm<<<out_grid, 256, MMA_SMEM>>>(Hh, woh, nullptr, out, 3);
}

// round 14
// speedup vs baseline: 1.1109x; 1.1109x over previous
#include <cuda_runtime.h>
#include <cuda_fp16.h>
#include <cstdint>

#define B_  4
#define S_  2048
#define D_  1024
#define H_  16
#define M_TOT 8192

// ---------------- device scratch (no allocs allowed) ----------------
__device__ __align__(256) __half g_qh[M_TOT * D_], g_ql[M_TOT * D_];
__device__ __align__(256) __half g_kh[M_TOT * D_], g_kl[M_TOT * D_];
__device__ __align__(256) __half g_vh[M_TOT * D_];
__device__ __align__(256) __half g_wqh[H_ * 64 * D_], g_wql[H_ * 64 * D_];
__device__ __align__(256) __half g_wkh[H_ * 64 * D_], g_wkl[H_ * 64 * D_];
__device__ __align__(256) __half g_wvh[H_ * 64 * D_];
__device__ __align__(256) __half g_woh[D_ * D_];
__device__ __align__(256) __half g_Qh[64 * S_ * 64];     // [bh][s][dk] hi only (pre-scaled)
__device__ __align__(256) __half g_Kh[64 * S_ * 64];     // [bh][key][dk] hi only (3-term-accurate, rounded once)
__device__ __align__(256) __half g_Vth[64 * 64 * S_];    // [bh][dv][key] hi only
__device__ __align__(256) __half g_Hh[M_TOT * D_];       // hi only

// ---------------- PTX helpers (baseline ISA: sm_80+) ----------------
__device__ __forceinline__ uint32_t smem_u32(const void* p) {
    uint32_t a;
    asm("{ .reg .u64 t; cvta.to.shared.u64 t, %1; cvt.u32.u64 %0, t; }"
        : "=r"(a) : "l"(p));
    return a;
}
__device__ __forceinline__ void cp16(uint32_t dst, const void* src) {
    asm volatile("cp.async.cg.shared.global [%0], [%1], 16;"
                 :: "r"(dst), "l"(src) : "memory");
}
#define CP_COMMIT() asm volatile("cp.async.commit_group;" ::: "memory")
#define CP_WAIT1()  asm volatile("cp.async.wait_group 1;"  ::: "memory")
#define CP_WAIT0()  asm volatile("cp.async.wait_group 0;"  ::: "memory")

__device__ __forceinline__ void ldsm_x4(uint32_t* r, uint32_t addr) {
    asm volatile("ldmatrix.sync.aligned.m8n8.x4.shared.b16 {%0,%1,%2,%3}, [%4];"
                 : "=r"(r[0]), "=r"(r[1]), "=r"(r[2]), "=r"(r[3]) : "r"(addr));
}
// fp16 inputs, fp32 accumulate (fastest legacy path per r7/r8 measurements)
__device__ __forceinline__ void hmma(float* d, const uint32_t* a,
                                     uint32_t b0, uint32_t b1) {
    asm volatile("mma.sync.aligned.m16n8k16.row.col.f32.f16.f16.f32 "
                 "{%0,%1,%2,%3}, {%4,%5,%6,%7}, {%8,%9}, {%0,%1,%2,%3};"
                 : "+f"(d[0]), "+f"(d[1]), "+f"(d[2]), "+f"(d[3])
                 : "r"(a[0]), "r"(a[1]), "r"(a[2]), "r"(a[3]), "r"(b0), "r"(b1));
}
__device__ __forceinline__ uint32_t swz(uint32_t off) {
    return off ^ ((off >> 3) & 0x70);
}
__device__ __forceinline__ void split_f16(float x, __half& h, __half& l) {
    h = __float2half_rn(x);
    l = __float2half_rn(x - __half2float(h));
}
__device__ __forceinline__ uint32_t pack2(float x, float y) {
    __half2 h = __floats2half2_rn(x, y);
    return *reinterpret_cast<uint32_t*>(&h);
}

// ---------------- conversion kernels (fused) ----------------
__global__ __launch_bounds__(256) void conv_in3(const float* __restrict__ q,
                                                const float* __restrict__ k,
                                                const float* __restrict__ v)
{
    const int which = blockIdx.y;
    const float* x = (which == 0) ? q : ((which == 1) ? k : v);
    __half* hi = (which == 0) ? g_qh : ((which == 1) ? g_kh : g_vh);
    __half* lo = (which == 0) ? g_ql : g_kl;   // V needs no lo (1-term proj)
    size_t i = ((size_t)blockIdx.x * 256 + threadIdx.x) * 4;
    float4 vv = *reinterpret_cast<const float4*>(x + i);
    __half h0, h1, h2, h3, l0, l1, l2, l3;
    split_f16(vv.x, h0, l0); split_f16(vv.y, h1, l1);
    split_f16(vv.z, h2, l2); split_f16(vv.w, h3, l3);
    *reinterpret_cast<__half2*>(hi + i)     = __halves2half2(h0, h1);
    *reinterpret_cast<__half2*>(hi + i + 2) = __halves2half2(h2, h3);
    if (which != 2) {
        *reinterpret_cast<__half2*>(lo + i)     = __halves2half2(l0, l1);
        *reinterpret_cast<__half2*>(lo + i + 2) = __halves2half2(l2, l3);
    }
}

// z=0..2: W[h][k][n] (16,1024,64) -> Wt[h][n][k] hi (and lo for Q/K)
// z=3:    Wo[k][n] (1024,1024) -> Wot[n][k] hi
__global__ __launch_bounds__(256) void conv_w4(const float* __restrict__ Wq,
                                               const float* __restrict__ Wk,
                                               const float* __restrict__ Wv,
                                               const float* __restrict__ Wo)
{
    const int which = blockIdx.y;
    int idx = blockIdx.x * 256 + threadIdx.x;
    if (which == 3) {
        int k = idx & 1023;
        int n = idx >> 10;
        g_woh[idx] = __float2half_rn(Wo[(size_t)k * D_ + n]);
        return;
    }
    const float* W = (which == 0) ? Wq : ((which == 1) ? Wk : Wv);
    __half* hi = (which == 0) ? g_wqh : ((which == 1) ? g_wkh : g_wvh);
    __half* lo = (which == 0) ? g_wql : g_wkl;
    int k = idx & 1023;
    int n = (idx >> 10) & 63;
    int h = idx >> 16;
    float x = W[((size_t)h * D_ + k) * 64 + n];
    __half hh, ll;
    split_f16(x, hh, ll);
    hi[idx] = hh;
    if (which != 2) lo[idx] = ll;
}

// ---------------- split-fp16 HMMA GEMM (256 thr, 8 warps x 16 rows) ----------------
// terms per mode: Q(0)=3, K(1)=3 (accurate then rounded once), V(2)=1, out(3)=1.
// mode 4: z-merged Q/K/V projections.
#define STAGE_BYTES 49152
#define A_HI_OFF 0
#define A_LO_OFF 16384
#define B_HI_OFF 32768
#define B_LO_OFF 40960
#define MMA_SMEM (2 * STAGE_BYTES)

__global__ __launch_bounds__(256) void mma_gemm(const __half* __restrict__ ah_,
                                                const __half* __restrict__ bh_,
                                                const __half* __restrict__ bl_,
                                                float* __restrict__ outp, int mode)
{
    extern __shared__ char sm[];
    const uint32_t smem = smem_u32(sm);
    const int tid  = threadIdx.x;
    const int wid  = tid >> 5;
    const int lane = tid & 31;
    const int nb   = blockIdx.x;
    const int m0   = blockIdx.y * 128;
    const int mbase = wid * 16;

    int emode = mode;
    const __half *ah = ah_, *al = nullptr, *bh = bh_, *bl = bl_;
    if (mode == 4) {
        const int z = blockIdx.z;          // 0=Q 1=K 2=V
        emode = z;
        ah = (z == 0) ? g_qh : ((z == 1) ? g_kh : g_vh);
        al = (z == 0) ? g_ql : g_kl;
        bh = (z == 0) ? g_wqh : ((z == 1) ? g_wkh : g_wvh);
        bl = (z == 0) ? g_wql : g_wkl;
    }
    const int nt = (emode <= 1) ? 3 : 1;   // Q/K: 3-term; V/out: 1-term

    const __half* aH = ah + (size_t)m0 * D_;
    const __half* aL = (nt >= 3) ? (al + (size_t)m0 * D_) : nullptr;
    const __half* bH = bh + (size_t)nb * 64 * D_;
    const __half* bL = (nt >= 2) ? (bl + (size_t)nb * 64 * D_) : nullptr;

    const int arow = tid >> 1, ahalf = tid & 1;
    const int brow_ = tid >> 2, bq = tid & 3;
    auto load_stage = [&](int c, int buf) {
        const uint32_t sb = smem + buf * STAGE_BYTES;
        const int k0 = c * 64;
        const char* gh = (const char*)(aH + (size_t)arow * D_ + k0) + ahalf * 64;
        #pragma unroll
        for (int j = 0; j < 4; ++j) {
            uint32_t sw = swz(arow * 128 + ahalf * 64 + j * 16);
            cp16(sb + A_HI_OFF + sw, gh + j * 16);
            if (nt >= 3) {
                const char* gl = (const char*)(aL + (size_t)arow * D_ + k0) + ahalf * 64;
                cp16(sb + A_LO_OFF + sw, gl + j * 16);
            }
        }
        const char* gbh = (const char*)(bH + (size_t)brow_ * D_ + k0) + bq * 32;
        #pragma unroll
        for (int j = 0; j < 2; ++j) {
            uint32_t sw = swz(brow_ * 128 + bq * 32 + j * 16);
            cp16(sb + B_HI_OFF + sw, gbh + j * 16);
            if (nt >= 2) {
                const char* gbl = (const char*)(bL + (size_t)brow_ * D_ + k0) + bq * 32;
                cp16(sb + B_LO_OFF + sw, gbl + j * 16);
            }
        }
    };

    float acc[8][4] = {};

    load_stage(0, 0);
    CP_COMMIT();

    for (int c = 0; c < 16; ++c) {
        const int buf = c & 1;
        if (c < 15) { load_stage(c + 1, buf ^ 1); CP_COMMIT(); }
        if (c < 15) CP_WAIT1(); else CP_WAIT0();
        __syncthreads();

        const uint32_t sb = smem + buf * STAGE_BYTES;
        #pragma unroll
        for (int ks = 0; ks < 4; ++ks) {
            const int kb = ks * 32;
            uint32_t ahi[4], alo[4];
            {
                uint32_t off = (uint32_t)(mbase + (lane & 15)) * 128
                             + kb + (lane >> 4) * 16;
                uint32_t sw = swz(off);
                ldsm_x4(ahi, sb + A_HI_OFF + sw);
                if (nt >= 3) ldsm_x4(alo, sb + A_LO_OFF + sw);
            }
            uint32_t bhi[4][4], blo[4][4];
            #pragma unroll
            for (int np = 0; np < 4; ++np) {
                uint32_t n  = np * 16 + (lane & 7) + ((lane >> 4) << 3);
                uint32_t off = n * 128 + kb + ((lane >> 3) & 1) * 16;
                uint32_t sw = swz(off);
                ldsm_x4(bhi[np], sb + B_HI_OFF + sw);
                if (nt >= 2) ldsm_x4(blo[np], sb + B_LO_OFF + sw);
            }
            #pragma unroll
            for (int nf = 0; nf < 8; ++nf) {
                const int np = nf >> 1, sel = (nf & 1) * 2;
                hmma(acc[nf], ahi, bhi[np][sel], bhi[np][sel + 1]);
            }
            if (nt >= 2) {
                #pragma unroll
                for (int nf = 0; nf < 8; ++nf) {
                    const int np = nf >> 1, sel = (nf & 1) * 2;
                    hmma(acc[nf], ahi, blo[np][sel], blo[np][sel + 1]);
                }
            }
            if (nt >= 3) {
                #pragma unroll
                for (int nf = 0; nf < 8; ++nf) {
                    const int np = nf >> 1, sel = (nf & 1) * 2;
                    hmma(acc[nf], alo, bhi[np][sel], bhi[np][sel + 1]);
                }
            }
        }
        __syncthreads();
    }

    // ---- epilogue ----
    const int g = lane >> 2;
    const int t = lane & 3;
    #pragma unroll
    for (int half = 0; half < 2; ++half) {
        const int m = m0 + mbase + half * 8 + g;
        if (emode == 3) {
            float* orow = outp + (size_t)m * D_ + nb * 64;
            #pragma unroll
            for (int nf = 0; nf < 8; ++nf)
                *reinterpret_cast<float2*>(orow + nf * 8 + t * 2) =
                    make_float2(acc[nf][half * 2], acc[nf][half * 2 + 1]);
        } else {
            const int b = m >> 11, s = m & (S_ - 1);
            const int bh_i = b * H_ + nb;
            if (emode == 0) {
                // Q: hi only, pre-scaled
                size_t base = ((size_t)bh_i * S_ + s) * 64;
                #pragma unroll
                for (int nf = 0; nf < 8; ++nf)
                    *reinterpret_cast<uint32_t*>(g_Qh + base + nf * 8 + t * 2) =
                        pack2(acc[nf][half * 2] * 0.125f, acc[nf][half * 2 + 1] * 0.125f);
            } else if (emode == 1) {
                // K: hi only (rounded once from accurate 3-term f32)
                size_t base = ((size_t)bh_i * S_ + s) * 64;
                #pragma unroll
                for (int nf = 0; nf < 8; ++nf)
                    *reinterpret_cast<uint32_t*>(g_Kh + base + nf * 8 + t * 2) =
                        pack2(acc[nf][half * 2], acc[nf][half * 2 + 1]);
            } else {
                // V transpose: (s=key, dv) -> [bh][dv][key], hi only
                #pragma unroll
                for (int nf = 0; nf < 8; ++nf) {
                    #pragma unroll
                    for (int e = 0; e < 2; ++e) {
                        int dv = nf * 8 + t * 2 + e;
                        size_t addr = ((size_t)bh_i * 64 + dv) * S_ + s;
                        g_Vth[addr] = __float2half_rn(acc[nf][half * 2 + e]);
                    }
                }
            }
        }
    }
}

// ---------------- tensor-core flash attention (256 thr, 8 warps x 16 q-rows) ----------------
// 128-row q-tiles (r12 config — best measured). QK^T: 1-term. PV: 1-term.
#define KH_OFF 0
#define VH_OFF 8192
#define AT_STAGE 16384
#define QH_OFF (2 * AT_STAGE)
#define ATT_SMEM (QH_OFF + 16384)

__global__ __launch_bounds__(256) void attn_mma()
{
    extern __shared__ char sm[];
    const uint32_t smem = smem_u32(sm);
    const int tid  = threadIdx.x;
    const int wid  = tid >> 5;
    const int lane = tid & 31;
    const int bh   = blockIdx.y;
    const int q0   = blockIdx.x * 128;
    const int mbase = wid * 16;

    // Q tile async load (hi only)
    {
        const int row = tid >> 1, half = tid & 1;
        const char* gh = (const char*)(g_Qh + ((size_t)bh * S_ + q0 + row) * 64) + half * 64;
        #pragma unroll
        for (int i = 0; i < 4; ++i) {
            uint32_t sw = swz(row * 128 + half * 64 + i * 16);
            cp16(smem + QH_OFF + sw, gh + i * 16);
        }
    }
    const int r4 = tid >> 2, qq = tid & 3;
    auto load_stage = [&](int kt, int buf) {
        const uint32_t sb = smem + buf * AT_STAGE;
        const char* kh = (const char*)(g_Kh + ((size_t)bh * S_ + kt + r4) * 64) + qq * 32;
        const char* vh = (const char*)(g_Vth + ((size_t)bh * 64 + r4) * S_ + kt) + qq * 32;
        #pragma unroll
        for (int j = 0; j < 2; ++j) {
            uint32_t sw = swz(r4 * 128 + qq * 32 + j * 16);
            cp16(sb + KH_OFF + sw, kh + j * 16);
            cp16(sb + VH_OFF + sw, vh + j * 16);
        }
    };
    load_stage(0, 0);  CP_COMMIT();
    load_stage(64, 1); CP_COMMIT();
    CP_WAIT1();
    __syncthreads();

    // persistent Q hi fragments
    uint32_t qh[4][4];
    #pragma unroll
    for (int ks = 0; ks < 4; ++ks) {
        uint32_t off = (uint32_t)(mbase + (lane & 15)) * 128
                     + ks * 32 + (lane >> 4) * 16;
        ldsm_x4(qh[ks], smem + QH_OFF + swz(off));
    }

    float O[8][4] = {};
    float mrow[2] = {-1e30f, -1e30f};
    float lrow[2] = {};

    for (int c = 0; c < 32; ++c) {
        const uint32_t sb = smem + (c & 1) * AT_STAGE;

        // ---- QK^T (1-term: Qh*Kh) ----
        float s[8][4] = {};
        #pragma unroll
        for (int ks = 0; ks < 4; ++ks) {
            #pragma unroll
            for (int np2 = 0; np2 < 2; ++np2) {
                uint32_t kbh2[2][4];
                #pragma unroll
                for (int j = 0; j < 2; ++j) {
                    const int np = np2 * 2 + j;
                    uint32_t n  = np * 16 + (lane & 7) + ((lane >> 4) << 3);
                    uint32_t off = n * 128 + ks * 32 + ((lane >> 3) & 1) * 16;
                    ldsm_x4(kbh2[j], sb + KH_OFF + swz(off));
                }
                #pragma unroll
                for (int j = 0; j < 4; ++j) {
                    const int p = j >> 1, sel = (j & 1) * 2;
                    hmma(s[np2 * 4 + j], qh[ks], kbh2[p][sel], kbh2[p][sel + 1]);
                }
            }
        }

        // ---- online softmax (warp-uniform skip of rescale when max unchanged) ----
        #pragma unroll
        for (int half = 0; half < 2; ++half) {
            float rmax = -1e30f;
            #pragma unroll
            for (int nf = 0; nf < 8; ++nf)
                rmax = fmaxf(rmax, fmaxf(s[nf][half * 2], s[nf][half * 2 + 1]));
            rmax = fmaxf(rmax, __shfl_xor_sync(0xffffffffu, rmax, 1));
            rmax = fmaxf(rmax, __shfl_xor_sync(0xffffffffu, rmax, 2));
            if (__any_sync(0xffffffffu, rmax > mrow[half])) {
                const float mnew = fmaxf(mrow[half], rmax);
                const float corr = __expf(mrow[half] - mnew);
                lrow[half] *= corr;
                mrow[half] = mnew;
                #pragma unroll
                for (int nf = 0; nf < 8; ++nf) {
                    O[nf][half * 2]     *= corr;
                    O[nf][half * 2 + 1] *= corr;
                }
            }
            float rsum = 0.0f;
            #pragma unroll
            for (int nf = 0; nf < 8; ++nf) {
                float p0 = __expf(s[nf][half * 2]     - mrow[half]);
                float p1 = __expf(s[nf][half * 2 + 1] - mrow[half]);
                s[nf][half * 2]     = p0;
                s[nf][half * 2 + 1] = p1;
                rsum += p0 + p1;
            }
            rsum += __shfl_xor_sync(0xffffffffu, rsum, 1);
            rsum += __shfl_xor_sync(0xffffffffu, rsum, 2);
            lrow[half] += rsum;
        }

        // ---- P @ V (1-term: P rounded fp16, V hi) ----
        #pragma unroll
        for (int kk = 0; kk < 4; ++kk) {
            uint32_t pah[4];
            pah[0] = pack2(s[2 * kk][0],     s[2 * kk][1]);
            pah[1] = pack2(s[2 * kk][2],     s[2 * kk][3]);
            pah[2] = pack2(s[2 * kk + 1][0], s[2 * kk + 1][1]);
            pah[3] = pack2(s[2 * kk + 1][2], s[2 * kk + 1][3]);
            #pragma unroll
            for (int np2 = 0; np2 < 2; ++np2) {
                uint32_t vbh2[2][4];
                #pragma unroll
                for (int j = 0; j < 2; ++j) {
                    const int np = np2 * 2 + j;
                    uint32_t n  = np * 16 + (lane & 7) + ((lane >> 4) << 3);
                    uint32_t off = n * 128 + kk * 32 + ((lane >> 3) & 1) * 16;
                    ldsm_x4(vbh2[j], sb + VH_OFF + swz(off));
                }
                #pragma unroll
                for (int j = 0; j < 4; ++j) {
                    const int p = j >> 1, sel = (j & 1) * 2;
                    hmma(O[np2 * 4 + j], pah, vbh2[p][sel], vbh2[p][sel + 1]);
                }
            }
        }

        __syncthreads();
        if (c + 2 < 32) {
            load_stage((c + 2) * 64, c & 1);
            CP_COMMIT();
            CP_WAIT1();
        } else if (c + 1 < 32) {
            CP_WAIT0();
        }
        __syncthreads();
    }

    // ---- epilogue: normalize, round to fp16 hi, concat-head layout ----
    const int b = bh >> 4, h = bh & 15;
    const int g = lane >> 2, t = lane & 3;
    #pragma unroll
    for (int half = 0; half < 2; ++half) {
        const float inv = 1.0f / lrow[half];
        const int srow = q0 + mbase + half * 8 + g;
        size_t base = ((size_t)(b * S_ + srow)) * D_ + h * 64;
        #pragma unroll
        for (int nf = 0; nf < 8; ++nf) {
            uint32_t hi = pack2(O[nf][half * 2] * inv, O[nf][half * 2 + 1] * inv);
            *reinterpret_cast<uint32_t*>(g_Hh + base + nf * 8 + t * 2) = hi;
        }
    }
}

// ---------------- launch ----------------
extern "C" void kernel_launch(void* const* d_in, const int* in_sizes, int n_in,
                              void* d_out, int out_size)
{
    const float* q  = (const float*)d_in[0];
    const float* k  = (const float*)d_in[1];
    const float* v  = (const float*)d_in[2];
    const float* Wq = (const float*)d_in[3];
    const float* Wk = (const float*)d_in[4];
    const float* Wv = (const float*)d_in[5];
    const float* Wo = (const float*)d_in[6];
    float* out = (float*)d_out;

    static bool configured = false;
    if (!configured) {
        cudaFuncSetAttribute(mma_gemm, cudaFuncAttributeMaxDynamicSharedMemorySize, MMA_SMEM);
        cudaFuncSetAttribute(attn_mma, cudaFuncAttributeMaxDynamicSharedMemorySize, ATT_SMEM);
        configured = true;
    }

    __half *woh, *Hh;
    cudaGetSymbolAddress((void**)&woh, g_woh);
    cudaGetSymbolAddress((void**)&Hh, g_Hh);

    conv_in3<<<dim3(8192, 3), 256>>>(q, k, v);
    conv_w4<<<dim3(4096, 4), 256>>>(Wq, Wk, Wv, Wo);

    // merged Q/K/V projections: one launch, z = which (Q/K 3-term, V 1-term)
    dim3 proj_grid(H_, M_TOT / 128, 3);
    mma_gemm<<<proj_grid, 256, MMA_SMEM>>>(nullptr, nullptr, nullptr, nullptr, 4);

    dim3 attn_grid(S_ / 128, B_ * H_);   // 16 x 64
    attn_mma<<<attn_grid, 256, ATT_SMEM>>>();

    // out projection: 1-term (H hi, Wo hi)
    dim3 out_grid(D_ / 64, M_TOT / 128); // 16 x 64
    mma_gemm<<<out_grid, 256, MMA_SMEM>>>(Hh, woh, nullptr, out, 3);
}

// round 15
// speedup vs baseline: 1.1361x; 1.0227x over previous
#include <cuda_runtime.h>
#include <cuda_fp16.h>
#include <cstdint>

#define B_  4
#define S_  2048
#define D_  1024
#define H_  16
#define M_TOT 8192

// ---------------- device scratch (no allocs allowed) ----------------
__device__ __align__(256) __half g_qh[M_TOT * D_], g_ql[M_TOT * D_];
__device__ __align__(256) __half g_kh[M_TOT * D_], g_kl[M_TOT * D_];
__device__ __align__(256) __half g_vh[M_TOT * D_];
__device__ __align__(256) __half g_wqh[H_ * 64 * D_], g_wql[H_ * 64 * D_];
__device__ __align__(256) __half g_wkh[H_ * 64 * D_], g_wkl[H_ * 64 * D_];
__device__ __align__(256) __half g_wvh[H_ * 64 * D_];
__device__ __align__(256) __half g_woh[D_ * D_];
__device__ __align__(256) __half g_Qh[64 * S_ * 64];     // [bh][s][dk] hi only (pre-scaled)
__device__ __align__(256) __half g_Kh[64 * S_ * 64];     // [bh][key][dk] hi only (3-term-accurate, rounded once)
__device__ __align__(256) __half g_Vth[64 * 64 * S_];    // [bh][dv][key] hi only
__device__ __align__(256) __half g_Hh[M_TOT * D_];       // hi only

// ---------------- PTX helpers (baseline ISA: sm_80+) ----------------
__device__ __forceinline__ uint32_t smem_u32(const void* p) {
    uint32_t a;
    asm("{ .reg .u64 t; cvta.to.shared.u64 t, %1; cvt.u32.u64 %0, t; }"
        : "=r"(a) : "l"(p));
    return a;
}
__device__ __forceinline__ void cp16(uint32_t dst, const void* src) {
    asm volatile("cp.async.cg.shared.global [%0], [%1], 16;"
                 :: "r"(dst), "l"(src) : "memory");
}
#define CP_COMMIT() asm volatile("cp.async.commit_group;" ::: "memory")
#define CP_WAIT1()  asm volatile("cp.async.wait_group 1;"  ::: "memory")
#define CP_WAIT0()  asm volatile("cp.async.wait_group 0;"  ::: "memory")

__device__ __forceinline__ void ldsm_x4(uint32_t* r, uint32_t addr) {
    asm volatile("ldmatrix.sync.aligned.m8n8.x4.shared.b16 {%0,%1,%2,%3}, [%4];"
                 : "=r"(r[0]), "=r"(r[1]), "=r"(r[2]), "=r"(r[3]) : "r"(addr));
}
// fp16 inputs, fp32 accumulate (fastest legacy path per r7/r8 measurements)
__device__ __forceinline__ void hmma(float* d, const uint32_t* a,
                                     uint32_t b0, uint32_t b1) {
    asm volatile("mma.sync.aligned.m16n8k16.row.col.f32.f16.f16.f32 "
                 "{%0,%1,%2,%3}, {%4,%5,%6,%7}, {%8,%9}, {%0,%1,%2,%3};"
                 : "+f"(d[0]), "+f"(d[1]), "+f"(d[2]), "+f"(d[3])
                 : "r"(a[0]), "r"(a[1]), "r"(a[2]), "r"(a[3]), "r"(b0), "r"(b1));
}
__device__ __forceinline__ uint32_t swz(uint32_t off) {
    return off ^ ((off >> 3) & 0x70);
}
__device__ __forceinline__ void split_f16(float x, __half& h, __half& l) {
    h = __float2half_rn(x);
    l = __float2half_rn(x - __half2float(h));
}
__device__ __forceinline__ uint32_t pack2(float x, float y) {
    __half2 h = __floats2half2_rn(x, y);
    return *reinterpret_cast<uint32_t*>(&h);
}

// ---------------- conversion kernels (bandwidth-optimized) ----------------
// inputs: coalesced, 8 independent float4 per thread (MLP=8).
// grid (1024, 3): each block converts 8192 consecutive floats of one input.
__global__ __launch_bounds__(256) void conv_in3(const float* __restrict__ q,
                                                const float* __restrict__ k,
                                                const float* __restrict__ v)
{
    const int which = blockIdx.y;
    const float* x = (which == 0) ? q : ((which == 1) ? k : v);
    __half* hi = (which == 0) ? g_qh : ((which == 1) ? g_kh : g_vh);
    __half* lo = (which == 0) ? g_ql : g_kl;   // V needs no lo (1-term proj)
    const size_t base = (size_t)blockIdx.x * 8192 + threadIdx.x * 4;
    #pragma unroll
    for (int j = 0; j < 8; ++j) {
        size_t i = base + (size_t)j * 1024;
        float4 vv = *reinterpret_cast<const float4*>(x + i);
        __half h0, h1, h2, h3, l0, l1, l2, l3;
        split_f16(vv.x, h0, l0); split_f16(vv.y, h1, l1);
        split_f16(vv.z, h2, l2); split_f16(vv.w, h3, l3);
        *reinterpret_cast<__half2*>(hi + i)     = __halves2half2(h0, h1);
        *reinterpret_cast<__half2*>(hi + i + 2) = __halves2half2(h2, h3);
        if (which != 2) {
            *reinterpret_cast<__half2*>(lo + i)     = __halves2half2(l0, l1);
            *reinterpret_cast<__half2*>(lo + i + 2) = __halves2half2(l2, l3);
        }
    }
}

// weights: smem-tiled transpose, coalesced read AND write.
// grid (256, 4): job 0..2 = Wq/Wk/Wv [h][k][n]->[h][n][k]; job 3 = Wo [k][n]->[n][k].
__global__ __launch_bounds__(256) void conv_wt(const float* __restrict__ Wq,
                                               const float* __restrict__ Wk,
                                               const float* __restrict__ Wv,
                                               const float* __restrict__ Wo)
{
    __shared__ float tile[64][65];
    const int job = blockIdx.y;
    const int bx  = blockIdx.x;          // 0..255
    const int tid = threadIdx.x;
    const int r4  = tid >> 6;            // 0..3
    const int c64 = tid & 63;

    if (job < 3) {
        const float* W = (job == 0) ? Wq : ((job == 1) ? Wk : Wv);
        __half* hi = (job == 0) ? g_wqh : ((job == 1) ? g_wkh : g_wvh);
        __half* lo = (job == 0) ? g_wql : g_wkl;
        const int h  = bx >> 4;          // head 0..15
        const int kt = (bx & 15) * 64;   // k tile base
        #pragma unroll
        for (int it = 0; it < 16; ++it) {
            int kl = it * 4 + r4;
            tile[kl][c64] = W[((size_t)h * D_ + kt + kl) * 64 + c64];
        }
        __syncthreads();
        #pragma unroll
        for (int it = 0; it < 16; ++it) {
            int n = it * 4 + r4;
            float x = tile[c64][n];
            __half hh, ll;
            split_f16(x, hh, ll);
            size_t dst = (size_t)h * 65536 + (size_t)n * 1024 + kt + c64;
            hi[dst] = hh;
            if (job != 2) lo[dst] = ll;
        }
    } else {
        const int ntile = bx >> 4;
        const int kt = (bx & 15) * 64;
        const int n0 = ntile * 64;
        #pragma unroll
        for (int it = 0; it < 16; ++it) {
            int kl = it * 4 + r4;
            tile[kl][c64] = Wo[(size_t)(kt + kl) * D_ + n0 + c64];
        }
        __syncthreads();
        #pragma unroll
        for (int it = 0; it < 16; ++it) {
            int n = it * 4 + r4;
            g_woh[(size_t)(n0 + n) * 1024 + kt + c64] = __float2half_rn(tile[c64][n]);
        }
    }
}

// ---------------- split-fp16 HMMA GEMM (256 thr, 8 warps x 16 rows) ----------------
// terms per mode: Q(0)=3, K(1)=3 (accurate then rounded once), V(2)=1, out(3)=1.
// mode 4: z-merged Q/K/V projections.
#define STAGE_BYTES 49152
#define A_HI_OFF 0
#define A_LO_OFF 16384
#define B_HI_OFF 32768
#define B_LO_OFF 40960
#define MMA_SMEM (2 * STAGE_BYTES)

__global__ __launch_bounds__(256) void mma_gemm(const __half* __restrict__ ah_,
                                                const __half* __restrict__ bh_,
                                                const __half* __restrict__ bl_,
                                                float* __restrict__ outp, int mode)
{
    extern __shared__ char sm[];
    const uint32_t smem = smem_u32(sm);
    const int tid  = threadIdx.x;
    const int wid  = tid >> 5;
    const int lane = tid & 31;
    const int nb   = blockIdx.x;
    const int m0   = blockIdx.y * 128;
    const int mbase = wid * 16;

    int emode = mode;
    const __half *ah = ah_, *al = nullptr, *bh = bh_, *bl = bl_;
    if (mode == 4) {
        const int z = blockIdx.z;          // 0=Q 1=K 2=V
        emode = z;
        ah = (z == 0) ? g_qh : ((z == 1) ? g_kh : g_vh);
        al = (z == 0) ? g_ql : g_kl;
        bh = (z == 0) ? g_wqh : ((z == 1) ? g_wkh : g_wvh);
        bl = (z == 0) ? g_wql : g_wkl;
    }
    const int nt = (emode <= 1) ? 3 : 1;   // Q/K: 3-term; V/out: 1-term

    const __half* aH = ah + (size_t)m0 * D_;
    const __half* aL = (nt >= 3) ? (al + (size_t)m0 * D_) : nullptr;
    const __half* bH = bh + (size_t)nb * 64 * D_;
    const __half* bL = (nt >= 2) ? (bl + (size_t)nb * 64 * D_) : nullptr;

    const int arow = tid >> 1, ahalf = tid & 1;
    const int brow_ = tid >> 2, bq = tid & 3;
    auto load_stage = [&](int c, int buf) {
        const uint32_t sb = smem + buf * STAGE_BYTES;
        const int k0 = c * 64;
        const char* gh = (const char*)(aH + (size_t)arow * D_ + k0) + ahalf * 64;
        #pragma unroll
        for (int j = 0; j < 4; ++j) {
            uint32_t sw = swz(arow * 128 + ahalf * 64 + j * 16);
            cp16(sb + A_HI_OFF + sw, gh + j * 16);
            if (nt >= 3) {
                const char* gl = (const char*)(aL + (size_t)arow * D_ + k0) + ahalf * 64;
                cp16(sb + A_LO_OFF + sw, gl + j * 16);
            }
        }
        const char* gbh = (const char*)(bH + (size_t)brow_ * D_ + k0) + bq * 32;
        #pragma unroll
        for (int j = 0; j < 2; ++j) {
            uint32_t sw = swz(brow_ * 128 + bq * 32 + j * 16);
            cp16(sb + B_HI_OFF + sw, gbh + j * 16);
            if (nt >= 2) {
                const char* gbl = (const char*)(bL + (size_t)brow_ * D_ + k0) + bq * 32;
                cp16(sb + B_LO_OFF + sw, gbl + j * 16);
            }
        }
    };

    float acc[8][4] = {};

    load_stage(0, 0);
    CP_COMMIT();

    for (int c = 0; c < 16; ++c) {
        const int buf = c & 1;
        if (c < 15) { load_stage(c + 1, buf ^ 1); CP_COMMIT(); }
        if (c < 15) CP_WAIT1(); else CP_WAIT0();
        __syncthreads();

        const uint32_t sb = smem + buf * STAGE_BYTES;
        #pragma unroll
        for (int ks = 0; ks < 4; ++ks) {
            const int kb = ks * 32;
            uint32_t ahi[4], alo[4];
            {
                uint32_t off = (uint32_t)(mbase + (lane & 15)) * 128
                             + kb + (lane >> 4) * 16;
                uint32_t sw = swz(off);
                ldsm_x4(ahi, sb + A_HI_OFF + sw);
                if (nt >= 3) ldsm_x4(alo, sb + A_LO_OFF + sw);
            }
            uint32_t bhi[4][4], blo[4][4];
            #pragma unroll
            for (int np = 0; np < 4; ++np) {
                uint32_t n  = np * 16 + (lane & 7) + ((lane >> 4) << 3);
                uint32_t off = n * 128 + kb + ((lane >> 3) & 1) * 16;
                uint32_t sw = swz(off);
                ldsm_x4(bhi[np], sb + B_HI_OFF + sw);
                if (nt >= 2) ldsm_x4(blo[np], sb + B_LO_OFF + sw);
            }
            #pragma unroll
            for (int nf = 0; nf < 8; ++nf) {
                const int np = nf >> 1, sel = (nf & 1) * 2;
                hmma(acc[nf], ahi, bhi[np][sel], bhi[np][sel + 1]);
            }
            if (nt >= 2) {
                #pragma unroll
                for (int nf = 0; nf < 8; ++nf) {
                    const int np = nf >> 1, sel = (nf & 1) * 2;
                    hmma(acc[nf], ahi, blo[np][sel], blo[np][sel + 1]);
                }
            }
            if (nt >= 3) {
                #pragma unroll
                for (int nf = 0; nf < 8; ++nf) {
                    const int np = nf >> 1, sel = (nf & 1) * 2;
                    hmma(acc[nf], alo, bhi[np][sel], bhi[np][sel + 1]);
                }
            }
        }
        __syncthreads();
    }

    // ---- epilogue ----
    const int g = lane >> 2;
    const int t = lane & 3;
    #pragma unroll
    for (int half = 0; half < 2; ++half) {
        const int m = m0 + mbase + half * 8 + g;
        if (emode == 3) {
            float* orow = outp + (size_t)m * D_ + nb * 64;
            #pragma unroll
            for (int nf = 0; nf < 8; ++nf)
                *reinterpret_cast<float2*>(orow + nf * 8 + t * 2) =
                    make_float2(acc[nf][half * 2], acc[nf][half * 2 + 1]);
        } else {
            const int b = m >> 11, s = m & (S_ - 1);
            const int bh_i = b * H_ + nb;
            if (emode == 0) {
                // Q: hi only, pre-scaled
                size_t base = ((size_t)bh_i * S_ + s) * 64;
                #pragma unroll
                for (int nf = 0; nf < 8; ++nf)
                    *reinterpret_cast<uint32_t*>(g_Qh + base + nf * 8 + t * 2) =
                        pack2(acc[nf][half * 2] * 0.125f, acc[nf][half * 2 + 1] * 0.125f);
            } else if (emode == 1) {
                // K: hi only (rounded once from accurate 3-term f32)
                size_t base = ((size_t)bh_i * S_ + s) * 64;
                #pragma unroll
                for (int nf = 0; nf < 8; ++nf)
                    *reinterpret_cast<uint32_t*>(g_Kh + base + nf * 8 + t * 2) =
                        pack2(acc[nf][half * 2], acc[nf][half * 2 + 1]);
            } else {
                // V transpose: (s=key, dv) -> [bh][dv][key], hi only
                #pragma unroll
                for (int nf = 0; nf < 8; ++nf) {
                    #pragma unroll
                    for (int e = 0; e < 2; ++e) {
                        int dv = nf * 8 + t * 2 + e;
                        size_t addr = ((size_t)bh_i * 64 + dv) * S_ + s;
                        g_Vth[addr] = __float2half_rn(acc[nf][half * 2 + e]);
                    }
                }
            }
        }
    }
}

// ---------------- tensor-core flash attention (256 thr, 8 warps x 16 q-rows) ----------------
// 128-row q-tiles (best measured config). QK^T: 1-term. PV: 1-term.
#define KH_OFF 0
#define VH_OFF 8192
#define AT_STAGE 16384
#define QH_OFF (2 * AT_STAGE)
#define ATT_SMEM (QH_OFF + 16384)

__global__ __launch_bounds__(256) void attn_mma()
{
    extern __shared__ char sm[];
    const uint32_t smem = smem_u32(sm);
    const int tid  = threadIdx.x;
    const int wid  = tid >> 5;
    const int lane = tid & 31;
    const int bh   = blockIdx.y;
    const int q0   = blockIdx.x * 128;
    const int mbase = wid * 16;

    // Q tile async load (hi only)
    {
        const int row = tid >> 1, half = tid & 1;
        const char* gh = (const char*)(g_Qh + ((size_t)bh * S_ + q0 + row) * 64) + half * 64;
        #pragma unroll
        for (int i = 0; i < 4; ++i) {
            uint32_t sw = swz(row * 128 + half * 64 + i * 16);
            cp16(smem + QH_OFF + sw, gh + i * 16);
        }
    }
    const int r4 = tid >> 2, qq = tid & 3;
    auto load_stage = [&](int kt, int buf) {
        const uint32_t sb = smem + buf * AT_STAGE;
        const char* kh = (const char*)(g_Kh + ((size_t)bh * S_ + kt + r4) * 64) + qq * 32;
        const char* vh = (const char*)(g_Vth + ((size_t)bh * 64 + r4) * S_ + kt) + qq * 32;
        #pragma unroll
        for (int j = 0; j < 2; ++j) {
            uint32_t sw = swz(r4 * 128 + qq * 32 + j * 16);
            cp16(sb + KH_OFF + sw, kh + j * 16);
            cp16(sb + VH_OFF + sw, vh + j * 16);
        }
    };
    load_stage(0, 0);  CP_COMMIT();
    load_stage(64, 1); CP_COMMIT();
    CP_WAIT1();
    __syncthreads();

    // persistent Q hi fragments
    uint32_t qh[4][4];
    #pragma unroll
    for (int ks = 0; ks < 4; ++ks) {
        uint32_t off = (uint32_t)(mbase + (lane & 15)) * 128
                     + ks * 32 + (lane >> 4) * 16;
        ldsm_x4(qh[ks], smem + QH_OFF + swz(off));
    }

    float O[8][4] = {};
    float mrow[2] = {-1e30f, -1e30f};
    float lrow[2] = {};

    for (int c = 0; c < 32; ++c) {
        const uint32_t sb = smem + (c & 1) * AT_STAGE;

        // ---- QK^T (1-term: Qh*Kh) ----
        float s[8][4] = {};
        #pragma unroll
        for (int ks = 0; ks < 4; ++ks) {
            #pragma unroll
            for (int np2 = 0; np2 < 2; ++np2) {
                uint32_t kbh2[2][4];
                #pragma unroll
                for (int j = 0; j < 2; ++j) {
                    const int np = np2 * 2 + j;
                    uint32_t n  = np * 16 + (lane & 7) + ((lane >> 4) << 3);
                    uint32_t off = n * 128 + ks * 32 + ((lane >> 3) & 1) * 16;
                    ldsm_x4(kbh2[j], sb + KH_OFF + swz(off));
                }
                #pragma unroll
                for (int j = 0; j < 4; ++j) {
                    const int p = j >> 1, sel = (j & 1) * 2;
                    hmma(s[np2 * 4 + j], qh[ks], kbh2[p][sel], kbh2[p][sel + 1]);
                }
            }
        }

        // ---- online softmax (warp-uniform skip of rescale when max unchanged) ----
        #pragma unroll
        for (int half = 0; half < 2; ++half) {
            float rmax = -1e30f;
            #pragma unroll
            for (int nf = 0; nf < 8; ++nf)
                rmax = fmaxf(rmax, fmaxf(s[nf][half * 2], s[nf][half * 2 + 1]));
            rmax = fmaxf(rmax, __shfl_xor_sync(0xffffffffu, rmax, 1));
            rmax = fmaxf(rmax, __shfl_xor_sync(0xffffffffu, rmax, 2));
            if (__any_sync(0xffffffffu, rmax > mrow[half])) {
                const float mnew = fmaxf(mrow[half], rmax);
                const float corr = __expf(mrow[half] - mnew);
                lrow[half] *= corr;
                mrow[half] = mnew;
                #pragma unroll
                for (int nf = 0; nf < 8; ++nf) {
                    O[nf][half * 2]     *= corr;
                    O[nf][half * 2 + 1] *= corr;
                }
            }
            float rsum = 0.0f;
            #pragma unroll
            for (int nf = 0; nf < 8; ++nf) {
                float p0 = __expf(s[nf][half * 2]     - mrow[half]);
                float p1 = __expf(s[nf][half * 2 + 1] - mrow[half]);
                s[nf][half * 2]     = p0;
                s[nf][half * 2 + 1] = p1;
                rsum += p0 + p1;
            }
            rsum += __shfl_xor_sync(0xffffffffu, rsum, 1);
            rsum += __shfl_xor_sync(0xffffffffu, rsum, 2);
            lrow[half] += rsum;
        }

        // ---- P @ V (1-term: P rounded fp16, V hi) ----
        #pragma unroll
        for (int kk = 0; kk < 4; ++kk) {
            uint32_t pah[4];
            pah[0] = pack2(s[2 * kk][0],     s[2 * kk][1]);
            pah[1] = pack2(s[2 * kk][2],     s[2 * kk][3]);
            pah[2] = pack2(s[2 * kk + 1][0], s[2 * kk + 1][1]);
            pah[3] = pack2(s[2 * kk + 1][2], s[2 * kk + 1][3]);
            #pragma unroll
            for (int np2 = 0; np2 < 2; ++np2) {
                uint32_t vbh2[2][4];
                #pragma unroll
                for (int j = 0; j < 2; ++j) {
                    const int np = np2 * 2 + j;
                    uint32_t n  = np * 16 + (lane & 7) + ((lane >> 4) << 3);
                    uint32_t off = n * 128 + kk * 32 + ((lane >> 3) & 1) * 16;
                    ldsm_x4(vbh2[j], sb + VH_OFF + swz(off));
                }
                #pragma unroll
                for (int j = 0; j < 4; ++j) {
                    const int p = j >> 1, sel = (j & 1) * 2;
                    hmma(O[np2 * 4 + j], pah, vbh2[p][sel], vbh2[p][sel + 1]);
                }
            }
        }

        __syncthreads();
        if (c + 2 < 32) {
            load_stage((c + 2) * 64, c & 1);
            CP_COMMIT();
            CP_WAIT1();
        } else if (c + 1 < 32) {
            CP_WAIT0();
        }
        __syncthreads();
    }

    // ---- epilogue: normalize, round to fp16 hi, concat-head layout ----
    const int b = bh >> 4, h = bh & 15;
    const int g = lane >> 2, t = lane & 3;
    #pragma unroll
    for (int half = 0; half < 2; ++half) {
        const float inv = 1.0f / lrow[half];
        const int srow = q0 + mbase + half * 8 + g;
        size_t base = ((size_t)(b * S_ + srow)) * D_ + h * 64;
        #pragma unroll
        for (int nf = 0; nf < 8; ++nf) {
            uint32_t hi = pack2(O[nf][half * 2] * inv, O[nf][half * 2 + 1] * inv);
            *reinterpret_cast<uint32_t*>(g_Hh + base + nf * 8 + t * 2) = hi;
        }
    }
}

// ---------------- launch ----------------
extern "C" void kernel_launch(void* const* d_in, const int* in_sizes, int n_in,
                              void* d_out, int out_size)
{
    const float* q  = (const float*)d_in[0];
    const float* k  = (const float*)d_in[1];
    const float* v  = (const float*)d_in[2];
    const float* Wq = (const float*)d_in[3];
    const float* Wk = (const float*)d_in[4];
    const float* Wv = (const float*)d_in[5];
    const float* Wo = (const float*)d_in[6];
    float* out = (float*)d_out;

    static bool configured = false;
    if (!configured) {
        cudaFuncSetAttribute(mma_gemm, cudaFuncAttributeMaxDynamicSharedMemorySize, MMA_SMEM);
        cudaFuncSetAttribute(attn_mma, cudaFuncAttributeMaxDynamicSharedMemorySize, ATT_SMEM);
        configured = true;
    }

    __half *woh, *Hh;
    cudaGetSymbolAddress((void**)&woh, g_woh);
    cudaGetSymbolAddress((void**)&Hh, g_Hh);

    conv_in3<<<dim3(1024, 3), 256>>>(q, k, v);
    conv_wt<<<dim3(256, 4), 256>>>(Wq, Wk, Wv, Wo);

    // merged Q/K/V projections: one launch, z = which (Q/K 3-term, V 1-term)
    dim3 proj_grid(H_, M_TOT / 128, 3);
    mma_gemm<<<proj_grid, 256, MMA_SMEM>>>(nullptr, nullptr, nullptr, nullptr, 4);

    dim3 attn_grid(S_ / 128, B_ * H_);   // 16 x 64
    attn_mma<<<attn_grid, 256, ATT_SMEM>>>();

    // out projection: 1-term (H hi, Wo hi)
    dim3 out_grid(D_ / 64, M_TOT / 128); // 16 x 64
    mma_gemm<<<out_grid, 256, MMA_SMEM>>>(Hh, woh, nullptr, out, 3);
}

// round 16
// speedup vs baseline: 1.2132x; 1.0679x over previous
#include <cuda_runtime.h>
#include <cuda_fp16.h>
#include <cstdint>

#define B_  4
#define S_  2048
#define D_  1024
#define H_  16
#define M_TOT 8192

// ---------------- device scratch (no allocs allowed) ----------------
__device__ __align__(256) __half g_qh[M_TOT * D_];
__device__ __align__(256) __half g_kh[M_TOT * D_], g_kl[M_TOT * D_];
__device__ __align__(256) __half g_vh[M_TOT * D_];
__device__ __align__(256) __half g_wqh[H_ * 64 * D_], g_wql[H_ * 64 * D_];
__device__ __align__(256) __half g_wkh[H_ * 64 * D_], g_wkl[H_ * 64 * D_];
__device__ __align__(256) __half g_wvh[H_ * 64 * D_];
__device__ __align__(256) __half g_woh[D_ * D_];
__device__ __align__(256) __half g_Qh[64 * S_ * 64];     // [bh][s][dk] hi only (pre-scaled)
__device__ __align__(256) __half g_Kh[64 * S_ * 64];     // [bh][key][dk] hi only (3-term-accurate, rounded once)
__device__ __align__(256) __half g_Vth[64 * 64 * S_];    // [bh][dv][key] hi only
__device__ __align__(256) __half g_Hh[M_TOT * D_];       // hi only

// ---------------- PTX helpers (baseline ISA: sm_80+) ----------------
__device__ __forceinline__ uint32_t smem_u32(const void* p) {
    uint32_t a;
    asm("{ .reg .u64 t; cvta.to.shared.u64 t, %1; cvt.u32.u64 %0, t; }"
        : "=r"(a) : "l"(p));
    return a;
}
__device__ __forceinline__ void cp16(uint32_t dst, const void* src) {
    asm volatile("cp.async.cg.shared.global [%0], [%1], 16;"
                 :: "r"(dst), "l"(src) : "memory");
}
#define CP_COMMIT() asm volatile("cp.async.commit_group;" ::: "memory")
#define CP_WAIT1()  asm volatile("cp.async.wait_group 1;"  ::: "memory")
#define CP_WAIT0()  asm volatile("cp.async.wait_group 0;"  ::: "memory")

__device__ __forceinline__ void ldsm_x4(uint32_t* r, uint32_t addr) {
    asm volatile("ldmatrix.sync.aligned.m8n8.x4.shared.b16 {%0,%1,%2,%3}, [%4];"
                 : "=r"(r[0]), "=r"(r[1]), "=r"(r[2]), "=r"(r[3]) : "r"(addr));
}
// fp16 inputs, fp32 accumulate (fastest legacy path per r7/r8 measurements)
__device__ __forceinline__ void hmma(float* d, const uint32_t* a,
                                     uint32_t b0, uint32_t b1) {
    asm volatile("mma.sync.aligned.m16n8k16.row.col.f32.f16.f16.f32 "
                 "{%0,%1,%2,%3}, {%4,%5,%6,%7}, {%8,%9}, {%0,%1,%2,%3};"
                 : "+f"(d[0]), "+f"(d[1]), "+f"(d[2]), "+f"(d[3])
                 : "r"(a[0]), "r"(a[1]), "r"(a[2]), "r"(a[3]), "r"(b0), "r"(b1));
}
__device__ __forceinline__ uint32_t swz(uint32_t off) {
    return off ^ ((off >> 3) & 0x70);
}
__device__ __forceinline__ void split_f16(float x, __half& h, __half& l) {
    h = __float2half_rn(x);
    l = __float2half_rn(x - __half2float(h));
}
__device__ __forceinline__ uint32_t pack2(float x, float y) {
    __half2 h = __floats2half2_rn(x, y);
    return *reinterpret_cast<uint32_t*>(&h);
}

// ---------------- conversion kernels (bandwidth-optimized) ----------------
// inputs: coalesced, 8 independent float4 per thread (MLP=8).
// grid (1024, 3). lo written only for k (Q-proj is now 2-term A-hi-only).
__global__ __launch_bounds__(256) void conv_in3(const float* __restrict__ q,
                                                const float* __restrict__ k,
                                                const float* __restrict__ v)
{
    const int which = blockIdx.y;
    const float* x = (which == 0) ? q : ((which == 1) ? k : v);
    __half* hi = (which == 0) ? g_qh : ((which == 1) ? g_kh : g_vh);
    const size_t base = (size_t)blockIdx.x * 8192 + threadIdx.x * 4;
    #pragma unroll
    for (int j = 0; j < 8; ++j) {
        size_t i = base + (size_t)j * 1024;
        float4 vv = *reinterpret_cast<const float4*>(x + i);
        __half h0, h1, h2, h3, l0, l1, l2, l3;
        split_f16(vv.x, h0, l0); split_f16(vv.y, h1, l1);
        split_f16(vv.z, h2, l2); split_f16(vv.w, h3, l3);
        *reinterpret_cast<__half2*>(hi + i)     = __halves2half2(h0, h1);
        *reinterpret_cast<__half2*>(hi + i + 2) = __halves2half2(h2, h3);
        if (which == 1) {
            *reinterpret_cast<__half2*>(g_kl + i)     = __halves2half2(l0, l1);
            *reinterpret_cast<__half2*>(g_kl + i + 2) = __halves2half2(l2, l3);
        }
    }
}

// weights: smem-tiled transpose, coalesced read AND write.
// grid (256, 4): job 0..2 = Wq/Wk/Wv [h][k][n]->[h][n][k]; job 3 = Wo [k][n]->[n][k].
__global__ __launch_bounds__(256) void conv_wt(const float* __restrict__ Wq,
                                               const float* __restrict__ Wk,
                                               const float* __restrict__ Wv,
                                               const float* __restrict__ Wo)
{
    __shared__ float tile[64][65];
    const int job = blockIdx.y;
    const int bx  = blockIdx.x;          // 0..255
    const int tid = threadIdx.x;
    const int r4  = tid >> 6;            // 0..3
    const int c64 = tid & 63;

    if (job < 3) {
        const float* W = (job == 0) ? Wq : ((job == 1) ? Wk : Wv);
        __half* hi = (job == 0) ? g_wqh : ((job == 1) ? g_wkh : g_wvh);
        __half* lo = (job == 0) ? g_wql : g_wkl;
        const int h  = bx >> 4;          // head 0..15
        const int kt = (bx & 15) * 64;   // k tile base
        #pragma unroll
        for (int it = 0; it < 16; ++it) {
            int kl = it * 4 + r4;
            tile[kl][c64] = W[((size_t)h * D_ + kt + kl) * 64 + c64];
        }
        __syncthreads();
        #pragma unroll
        for (int it = 0; it < 16; ++it) {
            int n = it * 4 + r4;
            float x = tile[c64][n];
            __half hh, ll;
            split_f16(x, hh, ll);
            size_t dst = (size_t)h * 65536 + (size_t)n * 1024 + kt + c64;
            hi[dst] = hh;
            if (job != 2) lo[dst] = ll;
        }
    } else {
        const int ntile = bx >> 4;
        const int kt = (bx & 15) * 64;
        const int n0 = ntile * 64;
        #pragma unroll
        for (int it = 0; it < 16; ++it) {
            int kl = it * 4 + r4;
            tile[kl][c64] = Wo[(size_t)(kt + kl) * D_ + n0 + c64];
        }
        __syncthreads();
        #pragma unroll
        for (int it = 0; it < 16; ++it) {
            int n = it * 4 + r4;
            g_woh[(size_t)(n0 + n) * 1024 + kt + c64] = __float2half_rn(tile[c64][n]);
        }
    }
}

// ---------------- split-fp16 HMMA GEMM (256 thr, 8 warps x 16 rows) ----------------
// terms per mode: Q(0)=2 (xh*Wh + xh*Wl), K(1)=3, V(2)=1, out(3)=1. f32 accumulate.
// mode 4: z-merged Q/K/V projections.
#define STAGE_BYTES 49152
#define A_HI_OFF 0
#define A_LO_OFF 16384
#define B_HI_OFF 32768
#define B_LO_OFF 40960
#define MMA_SMEM (2 * STAGE_BYTES)

__global__ __launch_bounds__(256) void mma_gemm(const __half* __restrict__ ah_,
                                                const __half* __restrict__ bh_,
                                                const __half* __restrict__ bl_,
                                                float* __restrict__ outp, int mode)
{
    extern __shared__ char sm[];
    const uint32_t smem = smem_u32(sm);
    const int tid  = threadIdx.x;
    const int wid  = tid >> 5;
    const int lane = tid & 31;
    const int nb   = blockIdx.x;
    const int m0   = blockIdx.y * 128;
    const int mbase = wid * 16;

    int emode = mode;
    const __half *ah = ah_, *al = nullptr, *bh = bh_, *bl = bl_;
    if (mode == 4) {
        const int z = blockIdx.z;          // 0=Q 1=K 2=V
        emode = z;
        ah = (z == 0) ? g_qh : ((z == 1) ? g_kh : g_vh);
        al = g_kl;                          // only K uses an A-lo
        bh = (z == 0) ? g_wqh : ((z == 1) ? g_wkh : g_wvh);
        bl = (z == 0) ? g_wql : g_wkl;
    }
    // terms: K=3, Q=2, V/out=1
    const int nt = (emode == 1) ? 3 : ((emode == 0) ? 2 : 1);

    const __half* aH = ah + (size_t)m0 * D_;
    const __half* aL = (nt >= 3) ? (al + (size_t)m0 * D_) : nullptr;
    const __half* bH = bh + (size_t)nb * 64 * D_;
    const __half* bL = (nt >= 2) ? (bl + (size_t)nb * 64 * D_) : nullptr;

    const int arow = tid >> 1, ahalf = tid & 1;
    const int brow_ = tid >> 2, bq = tid & 3;
    auto load_stage = [&](int c, int buf) {
        const uint32_t sb = smem + buf * STAGE_BYTES;
        const int k0 = c * 64;
        const char* gh = (const char*)(aH + (size_t)arow * D_ + k0) + ahalf * 64;
        #pragma unroll
        for (int j = 0; j < 4; ++j) {
            uint32_t sw = swz(arow * 128 + ahalf * 64 + j * 16);
            cp16(sb + A_HI_OFF + sw, gh + j * 16);
            if (nt >= 3) {
                const char* gl = (const char*)(aL + (size_t)arow * D_ + k0) + ahalf * 64;
                cp16(sb + A_LO_OFF + sw, gl + j * 16);
            }
        }
        const char* gbh = (const char*)(bH + (size_t)brow_ * D_ + k0) + bq * 32;
        #pragma unroll
        for (int j = 0; j < 2; ++j) {
            uint32_t sw = swz(brow_ * 128 + bq * 32 + j * 16);
            cp16(sb + B_HI_OFF + sw, gbh + j * 16);
            if (nt >= 2) {
                const char* gbl = (const char*)(bL + (size_t)brow_ * D_ + k0) + bq * 32;
                cp16(sb + B_LO_OFF + sw, gbl + j * 16);
            }
        }
    };

    float acc[8][4] = {};

    load_stage(0, 0);
    CP_COMMIT();

    for (int c = 0; c < 16; ++c) {
        const int buf = c & 1;
        if (c < 15) { load_stage(c + 1, buf ^ 1); CP_COMMIT(); }
        if (c < 15) CP_WAIT1(); else CP_WAIT0();
        __syncthreads();

        const uint32_t sb = smem + buf * STAGE_BYTES;
        #pragma unroll
        for (int ks = 0; ks < 4; ++ks) {
            const int kb = ks * 32;
            uint32_t ahi[4], alo[4];
            {
                uint32_t off = (uint32_t)(mbase + (lane & 15)) * 128
                             + kb + (lane >> 4) * 16;
                uint32_t sw = swz(off);
                ldsm_x4(ahi, sb + A_HI_OFF + sw);
                if (nt >= 3) ldsm_x4(alo, sb + A_LO_OFF + sw);
            }
            uint32_t bhi[4][4], blo[4][4];
            #pragma unroll
            for (int np = 0; np < 4; ++np) {
                uint32_t n  = np * 16 + (lane & 7) + ((lane >> 4) << 3);
                uint32_t off = n * 128 + kb + ((lane >> 3) & 1) * 16;
                uint32_t sw = swz(off);
                ldsm_x4(bhi[np], sb + B_HI_OFF + sw);
                if (nt >= 2) ldsm_x4(blo[np], sb + B_LO_OFF + sw);
            }
            #pragma unroll
            for (int nf = 0; nf < 8; ++nf) {
                const int np = nf >> 1, sel = (nf & 1) * 2;
                hmma(acc[nf], ahi, bhi[np][sel], bhi[np][sel + 1]);
            }
            if (nt >= 2) {
                #pragma unroll
                for (int nf = 0; nf < 8; ++nf) {
                    const int np = nf >> 1, sel = (nf & 1) * 2;
                    hmma(acc[nf], ahi, blo[np][sel], blo[np][sel + 1]);
                }
            }
            if (nt >= 3) {
                #pragma unroll
                for (int nf = 0; nf < 8; ++nf) {
                    const int np = nf >> 1, sel = (nf & 1) * 2;
                    hmma(acc[nf], alo, bhi[np][sel], bhi[np][sel + 1]);
                }
            }
        }
        __syncthreads();
    }

    // ---- epilogue ----
    const int g = lane >> 2;
    const int t = lane & 3;
    #pragma unroll
    for (int half = 0; half < 2; ++half) {
        const int m = m0 + mbase + half * 8 + g;
        if (emode == 3) {
            float* orow = outp + (size_t)m * D_ + nb * 64;
            #pragma unroll
            for (int nf = 0; nf < 8; ++nf)
                *reinterpret_cast<float2*>(orow + nf * 8 + t * 2) =
                    make_float2(acc[nf][half * 2], acc[nf][half * 2 + 1]);
        } else {
            const int b = m >> 11, s = m & (S_ - 1);
            const int bh_i = b * H_ + nb;
            if (emode == 0) {
                // Q: hi only, pre-scaled
                size_t base = ((size_t)bh_i * S_ + s) * 64;
                #pragma unroll
                for (int nf = 0; nf < 8; ++nf)
                    *reinterpret_cast<uint32_t*>(g_Qh + base + nf * 8 + t * 2) =
                        pack2(acc[nf][half * 2] * 0.125f, acc[nf][half * 2 + 1] * 0.125f);
            } else if (emode == 1) {
                // K: hi only (rounded once from accurate 3-term f32)
                size_t base = ((size_t)bh_i * S_ + s) * 64;
                #pragma unroll
                for (int nf = 0; nf < 8; ++nf)
                    *reinterpret_cast<uint32_t*>(g_Kh + base + nf * 8 + t * 2) =
                        pack2(acc[nf][half * 2], acc[nf][half * 2 + 1]);
            } else {
                // V transpose: (s=key, dv) -> [bh][dv][key], hi only
                #pragma unroll
                for (int nf = 0; nf < 8; ++nf) {
                    #pragma unroll
                    for (int e = 0; e < 2; ++e) {
                        int dv = nf * 8 + t * 2 + e;
                        size_t addr = ((size_t)bh_i * 64 + dv) * S_ + s;
                        g_Vth[addr] = __float2half_rn(acc[nf][half * 2 + e]);
                    }
                }
            }
        }
    }
}

// ---------------- tensor-core flash attention (256 thr, 8 warps x 16 q-rows) ----------------
// 128-row q-tiles (best measured config). QK^T: 1-term. PV: 1-term.
#define KH_OFF 0
#define VH_OFF 8192
#define AT_STAGE 16384
#define QH_OFF (2 * AT_STAGE)
#define ATT_SMEM (QH_OFF + 16384)

__global__ __launch_bounds__(256) void attn_mma()
{
    extern __shared__ char sm[];
    const uint32_t smem = smem_u32(sm);
    const int tid  = threadIdx.x;
    const int wid  = tid >> 5;
    const int lane = tid & 31;
    const int bh   = blockIdx.y;
    const int q0   = blockIdx.x * 128;
    const int mbase = wid * 16;

    // Q tile async load (hi only)
    {
        const int row = tid >> 1, half = tid & 1;
        const char* gh = (const char*)(g_Qh + ((size_t)bh * S_ + q0 + row) * 64) + half * 64;
        #pragma unroll
        for (int i = 0; i < 4; ++i) {
            uint32_t sw = swz(row * 128 + half * 64 + i * 16);
            cp16(smem + QH_OFF + sw, gh + i * 16);
        }
    }
    const int r4 = tid >> 2, qq = tid & 3;
    auto load_stage = [&](int kt, int buf) {
        const uint32_t sb = smem + buf * AT_STAGE;
        const char* kh = (const char*)(g_Kh + ((size_t)bh * S_ + kt + r4) * 64) + qq * 32;
        const char* vh = (const char*)(g_Vth + ((size_t)bh * 64 + r4) * S_ + kt) + qq * 32;
        #pragma unroll
        for (int j = 0; j < 2; ++j) {
            uint32_t sw = swz(r4 * 128 + qq * 32 + j * 16);
            cp16(sb + KH_OFF + sw, kh + j * 16);
            cp16(sb + VH_OFF + sw, vh + j * 16);
        }
    };
    load_stage(0, 0);  CP_COMMIT();
    load_stage(64, 1); CP_COMMIT();
    CP_WAIT1();
    __syncthreads();

    // persistent Q hi fragments
    uint32_t qh[4][4];
    #pragma unroll
    for (int ks = 0; ks < 4; ++ks) {
        uint32_t off = (uint32_t)(mbase + (lane & 15)) * 128
                     + ks * 32 + (lane >> 4) * 16;
        ldsm_x4(qh[ks], smem + QH_OFF + swz(off));
    }

    float O[8][4] = {};
    float mrow[2] = {-1e30f, -1e30f};
    float lrow[2] = {};

    for (int c = 0; c < 32; ++c) {
        const uint32_t sb = smem + (c & 1) * AT_STAGE;

        // ---- QK^T (1-term: Qh*Kh) ----
        float s[8][4] = {};
        #pragma unroll
        for (int ks = 0; ks < 4; ++ks) {
            #pragma unroll
            for (int np2 = 0; np2 < 2; ++np2) {
                uint32_t kbh2[2][4];
                #pragma unroll
                for (int j = 0; j < 2; ++j) {
                    const int np = np2 * 2 + j;
                    uint32_t n  = np * 16 + (lane & 7) + ((lane >> 4) << 3);
                    uint32_t off = n * 128 + ks * 32 + ((lane >> 3) & 1) * 16;
                    ldsm_x4(kbh2[j], sb + KH_OFF + swz(off));
                }
                #pragma unroll
                for (int j = 0; j < 4; ++j) {
                    const int p = j >> 1, sel = (j & 1) * 2;
                    hmma(s[np2 * 4 + j], qh[ks], kbh2[p][sel], kbh2[p][sel + 1]);
                }
            }
        }

        // ---- online softmax (warp-uniform skip of rescale when max unchanged) ----
        #pragma unroll
        for (int half = 0; half < 2; ++half) {
            float rmax = -1e30f;
            #pragma unroll
            for (int nf = 0; nf < 8; ++nf)
                rmax = fmaxf(rmax, fmaxf(s[nf][half * 2], s[nf][half * 2 + 1]));
            rmax = fmaxf(rmax, __shfl_xor_sync(0xffffffffu, rmax, 1));
            rmax = fmaxf(rmax, __shfl_xor_sync(0xffffffffu, rmax, 2));
            if (__any_sync(0xffffffffu, rmax > mrow[half])) {
                const float mnew = fmaxf(mrow[half], rmax);
                const float corr = __expf(mrow[half] - mnew);
                lrow[half] *= corr;
                mrow[half] = mnew;
                #pragma unroll
                for (int nf = 0; nf < 8; ++nf) {
                    O[nf][half * 2]     *= corr;
                    O[nf][half * 2 + 1] *= corr;
                }
            }
            float rsum = 0.0f;
            #pragma unroll
            for (int nf = 0; nf < 8; ++nf) {
                float p0 = __expf(s[nf][half * 2]     - mrow[half]);
                float p1 = __expf(s[nf][half * 2 + 1] - mrow[half]);
                s[nf][half * 2]     = p0;
                s[nf][half * 2 + 1] = p1;
                rsum += p0 + p1;
            }
            rsum += __shfl_xor_sync(0xffffffffu, rsum, 1);
            rsum += __shfl_xor_sync(0xffffffffu, rsum, 2);
            lrow[half] += rsum;
        }

        // ---- P @ V (1-term: P rounded fp16, V hi) ----
        #pragma unroll
        for (int kk = 0; kk < 4; ++kk) {
            uint32_t pah[4];
            pah[0] = pack2(s[2 * kk][0],     s[2 * kk][1]);
            pah[1] = pack2(s[2 * kk][2],     s[2 * kk][3]);
            pah[2] = pack2(s[2 * kk + 1][0], s[2 * kk + 1][1]);
            pah[3] = pack2(s[2 * kk + 1][2], s[2 * kk + 1][3]);
            #pragma unroll
            for (int np2 = 0; np2 < 2; ++np2) {
                uint32_t vbh2[2][4];
                #pragma unroll
                for (int j = 0; j < 2; ++j) {
                    const int np = np2 * 2 + j;
                    uint32_t n  = np * 16 + (lane & 7) + ((lane >> 4) << 3);
                    uint32_t off = n * 128 + kk * 32 + ((lane >> 3) & 1) * 16;
                    ldsm_x4(vbh2[j], sb + VH_OFF + swz(off));
                }
                #pragma unroll
                for (int j = 0; j < 4; ++j) {
                    const int p = j >> 1, sel = (j & 1) * 2;
                    hmma(O[np2 * 4 + j], pah, vbh2[p][sel], vbh2[p][sel + 1]);
                }
            }
        }

        __syncthreads();
        if (c + 2 < 32) {
            load_stage((c + 2) * 64, c & 1);
            CP_COMMIT();
            CP_WAIT1();
        } else if (c + 1 < 32) {
            CP_WAIT0();
        }
        __syncthreads();
    }

    // ---- epilogue: normalize, round to fp16 hi, concat-head layout ----
    const int b = bh >> 4, h = bh & 15;
    const int g = lane >> 2, t = lane & 3;
    #pragma unroll
    for (int half = 0; half < 2; ++half) {
        const float inv = 1.0f / lrow[half];
        const int srow = q0 + mbase + half * 8 + g;
        size_t base = ((size_t)(b * S_ + srow)) * D_ + h * 64;
        #pragma unroll
        for (int nf = 0; nf < 8; ++nf) {
            uint32_t hi = pack2(O[nf][half * 2] * inv, O[nf][half * 2 + 1] * inv);
            *reinterpret_cast<uint32_t*>(g_Hh + base + nf * 8 + t * 2) = hi;
        }
    }
}

// ---------------- launch ----------------
extern "C" void kernel_launch(void* const* d_in, const int* in_sizes, int n_in,
                              void* d_out, int out_size)
{
    const float* q  = (const float*)d_in[0];
    const float* k  = (const float*)d_in[1];
    const float* v  = (const float*)d_in[2];
    const float* Wq = (const float*)d_in[3];
    const float* Wk = (const float*)d_in[4];
    const float* Wv = (const float*)d_in[5];
    const float* Wo = (const float*)d_in[6];
    float* out = (float*)d_out;

    static bool configured = false;
    if (!configured) {
        cudaFuncSetAttribute(mma_gemm, cudaFuncAttributeMaxDynamicSharedMemorySize, MMA_SMEM);
        cudaFuncSetAttribute(attn_mma, cudaFuncAttributeMaxDynamicSharedMemorySize, ATT_SMEM);
        configured = true;
    }

    __half *woh, *Hh;
    cudaGetSymbolAddress((void**)&woh, g_woh);
    cudaGetSymbolAddress((void**)&Hh, g_Hh);

    conv_in3<<<dim3(1024, 3), 256>>>(q, k, v);
    conv_wt<<<dim3(256, 4), 256>>>(Wq, Wk, Wv, Wo);

    // merged Q/K/V projections: one launch, z = which (Q 2-term, K 3-term, V 1-term)
    dim3 proj_grid(H_, M_TOT / 128, 3);
    mma_gemm<<<proj_grid, 256, MMA_SMEM>>>(nullptr, nullptr, nullptr, nullptr, 4);

    dim3 attn_grid(S_ / 128, B_ * H_);   // 16 x 64
    attn_mma<<<attn_grid, 256, ATT_SMEM>>>();

    // out projection: 1-term (H hi, Wo hi)
    dim3 out_grid(D_ / 64, M_TOT / 128); // 16 x 64
    mma_gemm<<<out_grid, 256, MMA_SMEM>>>(Hh, woh, nullptr, out, 3);
}